// round 13
// baseline (speedup 1.0000x reference)
#include <cuda_runtime.h>
#include <cuda_bf16.h>

#define D 64
#define MAXN 100032
#define MAXE 1600000
#define NEG_SLOPE 0.2f

// ---------------- scratch (static device memory; no allocs allowed) -------------
__device__ float4 g_Qt[64 * 16];  // Qt[r][h] = P[r][4h..4h+3]       (top: eh side)
__device__ float4 g_Qb[64 * 16];  // Qb[r][h] = P[r][64+4h..64+4h+3] (bot: et side)
__device__ int   g_is64;          // 1 if edge arrays are int64, 0 if int32
__device__ int   g_flag;          // spin-barrier counter for fused scan
__device__ int   g_deg[MAXN];
__device__ int   g_ptr[MAXN + 1];
__device__ int   g_cur[MAXN];
__device__ int   g_bsum[256];
__device__ int   g_packed[MAXE];  // (rel<<20) | tail
__device__ float g_embA[MAXN * D];

// ---------------- helpers ----------------
__device__ __forceinline__ float warp_sum(float v) {
    v += __shfl_xor_sync(0xffffffffu, v, 16);
    v += __shfl_xor_sync(0xffffffffu, v, 8);
    v += __shfl_xor_sync(0xffffffffu, v, 4);
    v += __shfl_xor_sync(0xffffffffu, v, 2);
    v += __shfl_xor_sync(0xffffffffu, v, 1);
    return v;
}

__device__ __forceinline__ int load_idx(const void* base, long long i, int is64) {
    if (is64) return (int)((const long long*)base)[i];
    return ((const int*)base)[i];
}

__device__ __forceinline__ float dot4(float4 a, float4 b) {
    return a.x * b.x + a.y * b.y + a.z * b.z + a.w * b.w;
}

// ---------------- fused init: zero deg + flag + precompute P + dtype detect -----
__global__ void k_init(const float* __restrict__ W, const float* __restrict__ rel,
                       const unsigned int* __restrict__ ew, int N) {
    int b = blockIdx.x, t = threadIdx.x;
    for (int i = b * 128 + t; i < N; i += 65 * 128) g_deg[i] = 0;
    if (b == 0 && t == 0) g_flag = 0;

    if (b < 64) {
        // P[r][j] = sum_d W[j][d] * rel[r][d]
        int j = t;  // 0..127
        const float* wrow = W + j * D;
        const float* rrow = rel + b * D;
        float s = 0.f;
#pragma unroll
        for (int d = 0; d < D; d++) s += wrow[d] * rrow[d];
        if (j < 64) ((float*)&g_Qt[b * 16 + (j >> 2)])[j & 3] = s;
        else { int jj = j - 64; ((float*)&g_Qb[b * 16 + (jj >> 2)])[jj & 3] = s; }
    } else if (t < 32) {
        // int64 LE values < 2^32 have all odd 32-bit words zero; int32 heads don't.
        unsigned int a = ew[2 * t + 1];
        unsigned int c = ew[2 * (t + 32) + 1];
        unsigned int nz = __ballot_sync(0xffffffffu, (a | c) != 0u);
        if (t == 0) g_is64 = (nz == 0u) ? 1 : 0;
    }
}

// ---------------- CSR build ----------------
__global__ void k_hist(const void* __restrict__ ei, int E) {
    int e = blockIdx.x * blockDim.x + threadIdx.x;
    if (e >= E) return;
    int head = load_idx(ei, e, g_is64);
    atomicAdd(&g_deg[head], 1);
}

// fused 3-phase scan in ONE kernel. gridDim.x <= 148 guarantees co-residency,
// so the spin barrier cannot deadlock. g_flag zeroed by k_init each launch.
__global__ void k_scan(int n, int E) {
    __shared__ int wsum[32];
    __shared__ int red2[33];
    int nb = gridDim.x;
    int i = blockIdx.x * 1024 + threadIdx.x;
    int lane = threadIdx.x & 31, wid = threadIdx.x >> 5;

    // phase 1: block-local inclusive scan (warp-shfl hierarchy)
    int v = (i < n) ? g_deg[i] : 0;
    int sc = v;
#pragma unroll
    for (int off = 1; off < 32; off <<= 1) {
        int t = __shfl_up_sync(0xffffffffu, sc, off);
        if (lane >= off) sc += t;
    }
    if (lane == 31) wsum[wid] = sc;
    __syncthreads();
    if (wid == 0) {
        int w = wsum[lane];
#pragma unroll
        for (int off = 1; off < 32; off <<= 1) {
            int t = __shfl_up_sync(0xffffffffu, w, off);
            if (lane >= off) w += t;
        }
        wsum[lane] = w;
    }
    __syncthreads();
    int incl = sc + ((wid > 0) ? wsum[wid - 1] : 0);

    // publish block total, then grid spin-barrier
    if (threadIdx.x == 1023) {
        g_bsum[blockIdx.x] = incl;
        __threadfence();
        atomicAdd(&g_flag, 1);
    }
    if (threadIdx.x == 0) {
        while (*(volatile int*)&g_flag < nb) { }
    }
    __syncthreads();

    // phase 2: block offset = sum of bsum[0..blockIdx-1] (warp 0..4 reduce)
    int part = (threadIdx.x < blockIdx.x) ? g_bsum[threadIdx.x] : 0;
    {
        int ws = part;
#pragma unroll
        for (int off = 16; off > 0; off >>= 1)
            ws += __shfl_xor_sync(0xffffffffu, ws, off);
        if (lane == 0) red2[wid] = ws;
    }
    __syncthreads();
    if (threadIdx.x == 0) {
        int offb = 0;
#pragma unroll
        for (int k = 0; k < 32; k++) offb += red2[k];
        red2[32] = offb;
    }
    __syncthreads();
    int offb = red2[32];

    // phase 3: apply offset
    if (i < n) {
        int p = incl - v + offb;
        g_ptr[i] = p;
        g_cur[i] = p;
    }
    if (i == 0) g_ptr[n] = E;
}

__global__ void k_place(const void* __restrict__ ei,
                        const void* __restrict__ et, int E) {
    int e = blockIdx.x * blockDim.x + threadIdx.x;
    if (e >= E) return;
    int is64 = g_is64;
    int head = load_idx(ei, e, is64);
    int tail = load_idx(ei, (long long)E + e, is64);
    int rt   = load_idx(et, e, is64);
    int pos = atomicAdd(&g_cur[head], 1);
    g_packed[pos] = (rt << 20) | tail;
}

// ---------------- one hop: warp per head node, QUARTER-WARP per edge ------------
// lane groups {0-7},{8-15},{16-23},{24-31} process edges base..base+3; each lane
// owns 8 dims (2x float4). FINAL=0: eout = normalized hop.
// FINAL=1: eout = 0.25*ent + 0.5*ein + normalized hop  (= res)
template <int FINAL>
__global__ __launch_bounds__(256)
void k_hop(const float* __restrict__ ein, float* __restrict__ eout,
           const float* __restrict__ ent, int N) {
    int warp = (blockIdx.x * blockDim.x + threadIdx.x) >> 5;
    int lane = threadIdx.x & 31;
    if (warp >= N) return;
    int grp = lane >> 3;       // 0..3: which edge of the 4-batch
    int gl  = lane & 7;        // 0..7: owns dims 8*gl .. 8*gl+7

    const float4 eh0 = *(const float4*)(ein + warp * D + 8 * gl);
    const float4 eh1 = *(const float4*)(ein + warp * D + 8 * gl + 4);
    int start = g_ptr[warp];
    int end   = g_ptr[warp + 1];

    float  s_lane = 0.f;
    float4 a0 = make_float4(0.f, 0.f, 0.f, 0.f);
    float4 a1 = make_float4(0.f, 0.f, 0.f, 0.f);

    for (int base = start; base < end; base += 4) {
        int e = base + grp;
        bool valid = (e < end);
        int pk = valid ? g_packed[e] : 0;
        int tail = pk & 0xFFFFF;
        int rt   = pk >> 20;

        float4 et0 = make_float4(0.f, 0.f, 0.f, 0.f), et1 = et0;
        float4 qt0 = et0, qt1 = et0, qb0 = et0, qb1 = et0;
        if (valid) {
            et0 = *(const float4*)(ein + tail * D + 8 * gl);
            et1 = *(const float4*)(ein + tail * D + 8 * gl + 4);
            qt0 = g_Qt[rt * 16 + 2 * gl];
            qt1 = g_Qt[rt * 16 + 2 * gl + 1];
            qb0 = g_Qb[rt * 16 + 2 * gl];
            qb1 = g_Qb[rt * 16 + 2 * gl + 1];
        }
        float part = dot4(eh0, qt0) + dot4(eh1, qt1)
                   + dot4(et0, qb0) + dot4(et1, qb1);
        // reduce within the 8-lane group (xor 4/2/1 never crosses groups)
        part += __shfl_xor_sync(0xffffffffu, part, 4);
        part += __shfl_xor_sync(0xffffffffu, part, 2);
        part += __shfl_xor_sync(0xffffffffu, part, 1);

        float logit = (part > 0.f) ? part : NEG_SLOPE * part;
        float w = valid ? __expf(logit) : 0.f;  // max-subtraction dropped: exact
        s_lane += w;                            // counted 8x per edge; /8 later
        a0.x += w * et0.x; a0.y += w * et0.y; a0.z += w * et0.z; a0.w += w * et0.w;
        a1.x += w * et1.x; a1.y += w * et1.y; a1.z += w * et1.z; a1.w += w * et1.w;
    }

    // combine the 4 groups' accumulators (xor 16 then 8)
#pragma unroll
    for (int off = 16; off >= 8; off >>= 1) {
        a0.x += __shfl_xor_sync(0xffffffffu, a0.x, off);
        a0.y += __shfl_xor_sync(0xffffffffu, a0.y, off);
        a0.z += __shfl_xor_sync(0xffffffffu, a0.z, off);
        a0.w += __shfl_xor_sync(0xffffffffu, a0.w, off);
        a1.x += __shfl_xor_sync(0xffffffffu, a1.x, off);
        a1.y += __shfl_xor_sync(0xffffffffu, a1.y, off);
        a1.z += __shfl_xor_sync(0xffffffffu, a1.z, off);
        a1.w += __shfl_xor_sync(0xffffffffu, a1.w, off);
    }
    float s = warp_sum(s_lane) * 0.125f;   // exact: /8 is a power of two

    float4 v0, v1;
    if (end > start) {
        float inv = 1.f / s;
        v0.x = eh0.x + a0.x * inv; v0.y = eh0.y + a0.y * inv;
        v0.z = eh0.z + a0.z * inv; v0.w = eh0.w + a0.w * inv;
        v1.x = eh1.x + a1.x * inv; v1.y = eh1.y + a1.y * inv;
        v1.z = eh1.z + a1.z * inv; v1.w = eh1.w + a1.w * inv;
    } else {
        v0 = eh0; v1 = eh1;        // agg = 0 for nodes with no out-edges
    }

    // row-wise L2 normalize (each dim appears once per group -> /4, exact)
    float nrm2 = warp_sum(dot4(v0, v0) + dot4(v1, v1)) * 0.25f;
    float nrm  = fmaxf(sqrtf(nrm2), 1e-12f);
    float inv_n = 1.f / nrm;
    v0.x *= inv_n; v0.y *= inv_n; v0.z *= inv_n; v0.w *= inv_n;
    v1.x *= inv_n; v1.y *= inv_n; v1.z *= inv_n; v1.w *= inv_n;

    if (FINAL) {
        const float4 e00 = *(const float4*)(ent + warp * D + 8 * gl);
        const float4 e01 = *(const float4*)(ent + warp * D + 8 * gl + 4);
        v0.x = 0.25f * e00.x + 0.5f * eh0.x + v0.x;
        v0.y = 0.25f * e00.y + 0.5f * eh0.y + v0.y;
        v0.z = 0.25f * e00.z + 0.5f * eh0.z + v0.z;
        v0.w = 0.25f * e00.w + 0.5f * eh0.w + v0.w;
        v1.x = 0.25f * e01.x + 0.5f * eh1.x + v1.x;
        v1.y = 0.25f * e01.y + 0.5f * eh1.y + v1.y;
        v1.z = 0.25f * e01.z + 0.5f * eh1.z + v1.z;
        v1.w = 0.25f * e01.w + 0.5f * eh1.w + v1.w;
    }
    if (grp == 0) {
        *(float4*)(eout + warp * D + 8 * gl)     = v0;
        *(float4*)(eout + warp * D + 8 * gl + 4) = v1;
    }
}

// ---------------- launch ----------------
extern "C" void kernel_launch(void* const* d_in, const int* in_sizes, int n_in,
                              void* d_out, int out_size) {
    const void*  ei  = d_in[0];                  // [2, E] int32 or int64
    const void*  et  = d_in[1];                  // [E]    int32 or int64
    const float* ent = (const float*)d_in[2];    // [N, 64]
    const float* rel = (const float*)d_in[3];    // [R, 64]
    const float* W   = (const float*)d_in[4];    // [128, 64]
    float*       res = (float*)d_out;            // [N, 64]

    int E = in_sizes[0] / 2;
    int N = in_sizes[2] / D;

    void* p_embA;
    cudaGetSymbolAddress(&p_embA, g_embA);

    // fused: zero deg/flag + precompute P + dtype detect
    k_init<<<65, 128>>>(W, rel, (const unsigned int*)ei, N);

    // CSR build
    int egrid = (E + 255) / 256;
    k_hist<<<egrid, 256>>>(ei, E);
    int nblk = (N + 1023) / 1024;    // 98 <= 148: co-residency guaranteed
    k_scan<<<nblk, 1024>>>(N, E);
    k_place<<<egrid, 256>>>(ei, et, E);

    // hop 1: ent -> g_embA ; hop 2: g_embA -> res (with fused residual)
    int hgrid = (N + 7) / 8;   // 8 warps per 256-thread block
    k_hop<0><<<hgrid, 256>>>(ent, (float*)p_embA, ent, N);
    k_hop<1><<<hgrid, 256>>>((float*)p_embA, res, ent, N);
}

// round 14
// speedup vs baseline: 1.0011x; 1.0011x over previous
#include <cuda_runtime.h>
#include <cuda_bf16.h>

#define D 64
#define MAXN 100032
#define MAXE 1600000
#define NEG_SLOPE 0.2f

// ---------------- scratch (static device memory; no allocs allowed) -------------
__device__ float4 g_Qt[64 * 16];  // Qt[r][h] = P[r][4h..4h+3]       (top: eh side)
__device__ float4 g_Qb[64 * 16];  // Qb[r][h] = P[r][64+4h..64+4h+3] (bot: et side)
__device__ int   g_is64;          // 1 if edge arrays are int64, 0 if int32
__device__ int   g_flag;          // spin-barrier counter for fused scan
__device__ int   g_deg[MAXN];
__device__ int   g_ptr[MAXN + 1];
__device__ int   g_cur[MAXN];
__device__ int   g_bsum[256];
__device__ int   g_packed[MAXE];  // (rel<<20) | tail
__device__ float g_embA[MAXN * D];

// ---------------- helpers ----------------
__device__ __forceinline__ float warp_sum(float v) {
    v += __shfl_xor_sync(0xffffffffu, v, 16);
    v += __shfl_xor_sync(0xffffffffu, v, 8);
    v += __shfl_xor_sync(0xffffffffu, v, 4);
    v += __shfl_xor_sync(0xffffffffu, v, 2);
    v += __shfl_xor_sync(0xffffffffu, v, 1);
    return v;
}

__device__ __forceinline__ int load_idx(const void* base, long long i, int is64) {
    if (is64) return (int)((const long long*)base)[i];
    return ((const int*)base)[i];
}

__device__ __forceinline__ float dot4(float4 a, float4 b) {
    return a.x * b.x + a.y * b.y + a.z * b.z + a.w * b.w;
}

// ---------------- fused init: zero deg + flag + precompute P + dtype detect -----
__global__ void k_init(const float* __restrict__ W, const float* __restrict__ rel,
                       const unsigned int* __restrict__ ew, int N) {
    int b = blockIdx.x, t = threadIdx.x;
    for (int i = b * 128 + t; i < N; i += 65 * 128) g_deg[i] = 0;
    if (b == 0 && t == 0) g_flag = 0;

    if (b < 64) {
        // P[r][j] = sum_d W[j][d] * rel[r][d]
        int j = t;  // 0..127
        const float* wrow = W + j * D;
        const float* rrow = rel + b * D;
        float s = 0.f;
#pragma unroll
        for (int d = 0; d < D; d++) s += wrow[d] * rrow[d];
        if (j < 64) ((float*)&g_Qt[b * 16 + (j >> 2)])[j & 3] = s;
        else { int jj = j - 64; ((float*)&g_Qb[b * 16 + (jj >> 2)])[jj & 3] = s; }
    } else if (t < 32) {
        // int64 LE values < 2^32 have all odd 32-bit words zero; int32 heads don't.
        unsigned int a = ew[2 * t + 1];
        unsigned int c = ew[2 * (t + 32) + 1];
        unsigned int nz = __ballot_sync(0xffffffffu, (a | c) != 0u);
        if (t == 0) g_is64 = (nz == 0u) ? 1 : 0;
    }
}

// ---------------- CSR build ----------------
__global__ void k_hist(const void* __restrict__ ei, int E) {
    int e = blockIdx.x * blockDim.x + threadIdx.x;
    if (e >= E) return;
    int head = load_idx(ei, e, g_is64);
    atomicAdd(&g_deg[head], 1);
}

// fused 3-phase scan in ONE kernel. gridDim.x <= 148 guarantees co-residency,
// so the spin barrier cannot deadlock. g_flag zeroed by k_init each launch.
__global__ void k_scan(int n, int E) {
    __shared__ int wsum[32];
    __shared__ int red2[33];
    int nb = gridDim.x;
    int i = blockIdx.x * 1024 + threadIdx.x;
    int lane = threadIdx.x & 31, wid = threadIdx.x >> 5;

    // phase 1: block-local inclusive scan (warp-shfl hierarchy)
    int v = (i < n) ? g_deg[i] : 0;
    int sc = v;
#pragma unroll
    for (int off = 1; off < 32; off <<= 1) {
        int t = __shfl_up_sync(0xffffffffu, sc, off);
        if (lane >= off) sc += t;
    }
    if (lane == 31) wsum[wid] = sc;
    __syncthreads();
    if (wid == 0) {
        int w = wsum[lane];
#pragma unroll
        for (int off = 1; off < 32; off <<= 1) {
            int t = __shfl_up_sync(0xffffffffu, w, off);
            if (lane >= off) w += t;
        }
        wsum[lane] = w;
    }
    __syncthreads();
    int incl = sc + ((wid > 0) ? wsum[wid - 1] : 0);

    // publish block total, then grid spin-barrier
    if (threadIdx.x == 1023) {
        g_bsum[blockIdx.x] = incl;
        __threadfence();
        atomicAdd(&g_flag, 1);
    }
    if (threadIdx.x == 0) {
        while (*(volatile int*)&g_flag < nb) { }
    }
    __syncthreads();

    // phase 2: block offset = sum of bsum[0..blockIdx-1] (warp 0..4 reduce)
    int part = (threadIdx.x < blockIdx.x) ? g_bsum[threadIdx.x] : 0;
    {
        int ws = part;
#pragma unroll
        for (int off = 16; off > 0; off >>= 1)
            ws += __shfl_xor_sync(0xffffffffu, ws, off);
        if (lane == 0) red2[wid] = ws;
    }
    __syncthreads();
    if (threadIdx.x == 0) {
        int offb = 0;
#pragma unroll
        for (int k = 0; k < 32; k++) offb += red2[k];
        red2[32] = offb;
    }
    __syncthreads();
    int offb = red2[32];

    // phase 3: apply offset
    if (i < n) {
        int p = incl - v + offb;
        g_ptr[i] = p;
        g_cur[i] = p;
    }
    if (i == 0) g_ptr[n] = E;
}

__global__ void k_place(const void* __restrict__ ei,
                        const void* __restrict__ et, int E) {
    int e = blockIdx.x * blockDim.x + threadIdx.x;
    if (e >= E) return;
    int is64 = g_is64;
    int head = load_idx(ei, e, is64);
    int tail = load_idx(ei, (long long)E + e, is64);
    int rt   = load_idx(et, e, is64);
    int pos = atomicAdd(&g_cur[head], 1);
    g_packed[pos] = (rt << 20) | tail;
}

// ---------------- one hop: warp per head node, QUARTER-WARP per edge ------------
// lane groups {0-7},{8-15},{16-23},{24-31} process edges base..base+3; each lane
// owns 8 dims (2x float4). FINAL=0: eout = normalized hop.
// FINAL=1: eout = 0.25*ent + 0.5*ein + normalized hop  (= res)
template <int FINAL>
__global__ __launch_bounds__(256)
void k_hop(const float* __restrict__ ein, float* __restrict__ eout,
           const float* __restrict__ ent, int N) {
    int warp = (blockIdx.x * blockDim.x + threadIdx.x) >> 5;
    int lane = threadIdx.x & 31;
    if (warp >= N) return;
    int grp = lane >> 3;       // 0..3: which edge of the 4-batch
    int gl  = lane & 7;        // 0..7: owns dims 8*gl .. 8*gl+7

    const float4 eh0 = *(const float4*)(ein + warp * D + 8 * gl);
    const float4 eh1 = *(const float4*)(ein + warp * D + 8 * gl + 4);
    int start = g_ptr[warp];
    int end   = g_ptr[warp + 1];

    float  s_lane = 0.f;
    float4 a0 = make_float4(0.f, 0.f, 0.f, 0.f);
    float4 a1 = make_float4(0.f, 0.f, 0.f, 0.f);

    for (int base = start; base < end; base += 4) {
        int e = base + grp;
        bool valid = (e < end);
        int pk = valid ? g_packed[e] : 0;
        int tail = pk & 0xFFFFF;
        int rt   = pk >> 20;

        float4 et0 = make_float4(0.f, 0.f, 0.f, 0.f), et1 = et0;
        float4 qt0 = et0, qt1 = et0, qb0 = et0, qb1 = et0;
        if (valid) {
            et0 = *(const float4*)(ein + tail * D + 8 * gl);
            et1 = *(const float4*)(ein + tail * D + 8 * gl + 4);
            qt0 = g_Qt[rt * 16 + 2 * gl];
            qt1 = g_Qt[rt * 16 + 2 * gl + 1];
            qb0 = g_Qb[rt * 16 + 2 * gl];
            qb1 = g_Qb[rt * 16 + 2 * gl + 1];
        }
        float part = dot4(eh0, qt0) + dot4(eh1, qt1)
                   + dot4(et0, qb0) + dot4(et1, qb1);
        // reduce within the 8-lane group (xor 4/2/1 never crosses groups)
        part += __shfl_xor_sync(0xffffffffu, part, 4);
        part += __shfl_xor_sync(0xffffffffu, part, 2);
        part += __shfl_xor_sync(0xffffffffu, part, 1);

        float logit = (part > 0.f) ? part : NEG_SLOPE * part;
        float w = valid ? __expf(logit) : 0.f;  // max-subtraction dropped: exact
        s_lane += w;                            // counted 8x per edge; /8 later
        a0.x += w * et0.x; a0.y += w * et0.y; a0.z += w * et0.z; a0.w += w * et0.w;
        a1.x += w * et1.x; a1.y += w * et1.y; a1.z += w * et1.z; a1.w += w * et1.w;
    }

    // combine the 4 groups' accumulators (xor 16 then 8)
#pragma unroll
    for (int off = 16; off >= 8; off >>= 1) {
        a0.x += __shfl_xor_sync(0xffffffffu, a0.x, off);
        a0.y += __shfl_xor_sync(0xffffffffu, a0.y, off);
        a0.z += __shfl_xor_sync(0xffffffffu, a0.z, off);
        a0.w += __shfl_xor_sync(0xffffffffu, a0.w, off);
        a1.x += __shfl_xor_sync(0xffffffffu, a1.x, off);
        a1.y += __shfl_xor_sync(0xffffffffu, a1.y, off);
        a1.z += __shfl_xor_sync(0xffffffffu, a1.z, off);
        a1.w += __shfl_xor_sync(0xffffffffu, a1.w, off);
    }
    float s = warp_sum(s_lane) * 0.125f;   // exact: /8 is a power of two

    float4 v0, v1;
    if (end > start) {
        float inv = 1.f / s;
        v0.x = eh0.x + a0.x * inv; v0.y = eh0.y + a0.y * inv;
        v0.z = eh0.z + a0.z * inv; v0.w = eh0.w + a0.w * inv;
        v1.x = eh1.x + a1.x * inv; v1.y = eh1.y + a1.y * inv;
        v1.z = eh1.z + a1.z * inv; v1.w = eh1.w + a1.w * inv;
    } else {
        v0 = eh0; v1 = eh1;        // agg = 0 for nodes with no out-edges
    }

    // row-wise L2 normalize (each dim appears once per group -> /4, exact)
    float nrm2 = warp_sum(dot4(v0, v0) + dot4(v1, v1)) * 0.25f;
    float nrm  = fmaxf(sqrtf(nrm2), 1e-12f);
    float inv_n = 1.f / nrm;
    v0.x *= inv_n; v0.y *= inv_n; v0.z *= inv_n; v0.w *= inv_n;
    v1.x *= inv_n; v1.y *= inv_n; v1.z *= inv_n; v1.w *= inv_n;

    if (FINAL) {
        const float4 e00 = *(const float4*)(ent + warp * D + 8 * gl);
        const float4 e01 = *(const float4*)(ent + warp * D + 8 * gl + 4);
        v0.x = 0.25f * e00.x + 0.5f * eh0.x + v0.x;
        v0.y = 0.25f * e00.y + 0.5f * eh0.y + v0.y;
        v0.z = 0.25f * e00.z + 0.5f * eh0.z + v0.z;
        v0.w = 0.25f * e00.w + 0.5f * eh0.w + v0.w;
        v1.x = 0.25f * e01.x + 0.5f * eh1.x + v1.x;
        v1.y = 0.25f * e01.y + 0.5f * eh1.y + v1.y;
        v1.z = 0.25f * e01.z + 0.5f * eh1.z + v1.z;
        v1.w = 0.25f * e01.w + 0.5f * eh1.w + v1.w;
    }
    if (grp == 0) {
        *(float4*)(eout + warp * D + 8 * gl)     = v0;
        *(float4*)(eout + warp * D + 8 * gl + 4) = v1;
    }
}

// ---------------- launch ----------------
extern "C" void kernel_launch(void* const* d_in, const int* in_sizes, int n_in,
                              void* d_out, int out_size) {
    const void*  ei  = d_in[0];                  // [2, E] int32 or int64
    const void*  et  = d_in[1];                  // [E]    int32 or int64
    const float* ent = (const float*)d_in[2];    // [N, 64]
    const float* rel = (const float*)d_in[3];    // [R, 64]
    const float* W   = (const float*)d_in[4];    // [128, 64]
    float*       res = (float*)d_out;            // [N, 64]

    int E = in_sizes[0] / 2;
    int N = in_sizes[2] / D;

    void* p_embA;
    cudaGetSymbolAddress(&p_embA, g_embA);

    // fused: zero deg/flag + precompute P + dtype detect
    k_init<<<65, 128>>>(W, rel, (const unsigned int*)ei, N);

    // CSR build
    int egrid = (E + 255) / 256;
    k_hist<<<egrid, 256>>>(ei, E);
    int nblk = (N + 1023) / 1024;    // 98 <= 148: co-residency guaranteed
    k_scan<<<nblk, 1024>>>(N, E);
    k_place<<<egrid, 256>>>(ei, et, E);

    // hop 1: ent -> g_embA ; hop 2: g_embA -> res (with fused residual)
    int hgrid = (N + 7) / 8;   // 8 warps per 256-thread block
    k_hop<0><<<hgrid, 256>>>(ent, (float*)p_embA, ent, N);
    k_hop<1><<<hgrid, 256>>>((float*)p_embA, res, ent, N);
}

// round 15
// speedup vs baseline: 1.0096x; 1.0085x over previous
#include <cuda_runtime.h>
#include <cuda_bf16.h>

#define D 64
#define MAXN 100032
#define MAXE 1600000
#define NEG_SLOPE 0.2f

// ---------------- scratch (static device memory; no allocs allowed) -------------
__device__ float4 g_Qt[64 * 16];  // Qt[r][h] = P[r][4h..4h+3]       (top: eh side)
__device__ float4 g_Qb[64 * 16];  // Qb[r][h] = P[r][64+4h..64+4h+3] (bot: et side)
__device__ int   g_is64;          // 1 if edge arrays are int64, 0 if int32
__device__ int   g_flag;          // spin-barrier counter for fused scan
__device__ int   g_deg[MAXN];
__device__ int   g_ptr[MAXN + 1];
__device__ int   g_cur[MAXN];
__device__ int   g_bsum[256];
__device__ int   g_packed[MAXE];  // (rel<<20) | tail
__device__ float g_embA[MAXN * D];

// ---------------- helpers ----------------
__device__ __forceinline__ float warp_sum(float v) {
    v += __shfl_xor_sync(0xffffffffu, v, 16);
    v += __shfl_xor_sync(0xffffffffu, v, 8);
    v += __shfl_xor_sync(0xffffffffu, v, 4);
    v += __shfl_xor_sync(0xffffffffu, v, 2);
    v += __shfl_xor_sync(0xffffffffu, v, 1);
    return v;
}

__device__ __forceinline__ int load_idx(const void* base, long long i, int is64) {
    if (is64) return (int)((const long long*)base)[i];
    return ((const int*)base)[i];
}

__device__ __forceinline__ float dot4(float4 a, float4 b) {
    return a.x * b.x + a.y * b.y + a.z * b.z + a.w * b.w;
}

// ---------------- fused init: zero deg + flag + precompute P + dtype detect -----
__global__ void k_init(const float* __restrict__ W, const float* __restrict__ rel,
                       const unsigned int* __restrict__ ew, int N) {
    int b = blockIdx.x, t = threadIdx.x;
    for (int i = b * 128 + t; i < N; i += 65 * 128) g_deg[i] = 0;
    if (b == 0 && t == 0) g_flag = 0;

    if (b < 64) {
        // P[r][j] = sum_d W[j][d] * rel[r][d]
        int j = t;  // 0..127
        const float* wrow = W + j * D;
        const float* rrow = rel + b * D;
        float s = 0.f;
#pragma unroll
        for (int d = 0; d < D; d++) s += wrow[d] * rrow[d];
        if (j < 64) ((float*)&g_Qt[b * 16 + (j >> 2)])[j & 3] = s;
        else { int jj = j - 64; ((float*)&g_Qb[b * 16 + (jj >> 2)])[jj & 3] = s; }
    } else if (t < 32) {
        // int64 LE values < 2^32 have all odd 32-bit words zero; int32 heads don't.
        unsigned int a = ew[2 * t + 1];
        unsigned int c = ew[2 * (t + 32) + 1];
        unsigned int nz = __ballot_sync(0xffffffffu, (a | c) != 0u);
        if (t == 0) g_is64 = (nz == 0u) ? 1 : 0;
    }
}

// ---------------- CSR build ----------------
__global__ void k_hist(const void* __restrict__ ei, int E) {
    int e = blockIdx.x * blockDim.x + threadIdx.x;
    if (e >= E) return;
    int head = load_idx(ei, e, g_is64);
    atomicAdd(&g_deg[head], 1);
}

// fused 3-phase scan in ONE kernel. gridDim.x <= 148 guarantees co-residency,
// so the spin barrier cannot deadlock. g_flag zeroed by k_init each launch.
__global__ void k_scan(int n, int E) {
    __shared__ int wsum[32];
    __shared__ int red2[33];
    int nb = gridDim.x;
    int i = blockIdx.x * 1024 + threadIdx.x;
    int lane = threadIdx.x & 31, wid = threadIdx.x >> 5;

    // phase 1: block-local inclusive scan (warp-shfl hierarchy)
    int v = (i < n) ? g_deg[i] : 0;
    int sc = v;
#pragma unroll
    for (int off = 1; off < 32; off <<= 1) {
        int t = __shfl_up_sync(0xffffffffu, sc, off);
        if (lane >= off) sc += t;
    }
    if (lane == 31) wsum[wid] = sc;
    __syncthreads();
    if (wid == 0) {
        int w = wsum[lane];
#pragma unroll
        for (int off = 1; off < 32; off <<= 1) {
            int t = __shfl_up_sync(0xffffffffu, w, off);
            if (lane >= off) w += t;
        }
        wsum[lane] = w;
    }
    __syncthreads();
    int incl = sc + ((wid > 0) ? wsum[wid - 1] : 0);

    // publish block total, then grid spin-barrier
    if (threadIdx.x == 1023) {
        g_bsum[blockIdx.x] = incl;
        __threadfence();
        atomicAdd(&g_flag, 1);
    }
    if (threadIdx.x == 0) {
        while (*(volatile int*)&g_flag < nb) { }
    }
    __syncthreads();

    // phase 2: block offset = sum of bsum[0..blockIdx-1] (warp 0..4 reduce)
    int part = (threadIdx.x < blockIdx.x) ? g_bsum[threadIdx.x] : 0;
    {
        int ws = part;
#pragma unroll
        for (int off = 16; off > 0; off >>= 1)
            ws += __shfl_xor_sync(0xffffffffu, ws, off);
        if (lane == 0) red2[wid] = ws;
    }
    __syncthreads();
    if (threadIdx.x == 0) {
        int offb = 0;
#pragma unroll
        for (int k = 0; k < 32; k++) offb += red2[k];
        red2[32] = offb;
    }
    __syncthreads();
    int offb = red2[32];

    // phase 3: apply offset
    if (i < n) {
        int p = incl - v + offb;
        g_ptr[i] = p;
        g_cur[i] = p;
    }
    if (i == 0) g_ptr[n] = E;
}

__global__ void k_place(const void* __restrict__ ei,
                        const void* __restrict__ et, int E) {
    int e = blockIdx.x * blockDim.x + threadIdx.x;
    if (e >= E) return;
    int is64 = g_is64;
    int head = load_idx(ei, e, is64);
    int tail = load_idx(ei, (long long)E + e, is64);
    int rt   = load_idx(et, e, is64);
    int pos = atomicAdd(&g_cur[head], 1);
    g_packed[pos] = (rt << 20) | tail;
}

// ---------------- one hop: warp per head node, QUARTER-WARP per edge ------------
// lane groups {0-7},{8-15},{16-23},{24-31} process edges base..base+3; each lane
// owns 8 dims (2x float4). FINAL=0: eout = normalized hop.
// FINAL=1: eout = 0.25*ent + 0.5*ein + normalized hop  (= res)
template <int FINAL>
__global__ __launch_bounds__(256)
void k_hop(const float* __restrict__ ein, float* __restrict__ eout,
           const float* __restrict__ ent, int N) {
    int warp = (blockIdx.x * blockDim.x + threadIdx.x) >> 5;
    int lane = threadIdx.x & 31;
    if (warp >= N) return;
    int grp = lane >> 3;       // 0..3: which edge of the 4-batch
    int gl  = lane & 7;        // 0..7: owns dims 8*gl .. 8*gl+7

    const float4 eh0 = *(const float4*)(ein + warp * D + 8 * gl);
    const float4 eh1 = *(const float4*)(ein + warp * D + 8 * gl + 4);
    int start = g_ptr[warp];
    int end   = g_ptr[warp + 1];

    float  s_lane = 0.f;
    float4 a0 = make_float4(0.f, 0.f, 0.f, 0.f);
    float4 a1 = make_float4(0.f, 0.f, 0.f, 0.f);

    for (int base = start; base < end; base += 4) {
        int e = base + grp;
        bool valid = (e < end);
        int pk = valid ? g_packed[e] : 0;
        int tail = pk & 0xFFFFF;
        int rt   = pk >> 20;

        float4 et0 = make_float4(0.f, 0.f, 0.f, 0.f), et1 = et0;
        float4 qt0 = et0, qt1 = et0, qb0 = et0, qb1 = et0;
        if (valid) {
            et0 = *(const float4*)(ein + tail * D + 8 * gl);
            et1 = *(const float4*)(ein + tail * D + 8 * gl + 4);
            qt0 = g_Qt[rt * 16 + 2 * gl];
            qt1 = g_Qt[rt * 16 + 2 * gl + 1];
            qb0 = g_Qb[rt * 16 + 2 * gl];
            qb1 = g_Qb[rt * 16 + 2 * gl + 1];
        }
        float part = dot4(eh0, qt0) + dot4(eh1, qt1)
                   + dot4(et0, qb0) + dot4(et1, qb1);
        // reduce within the 8-lane group (xor 4/2/1 never crosses groups)
        part += __shfl_xor_sync(0xffffffffu, part, 4);
        part += __shfl_xor_sync(0xffffffffu, part, 2);
        part += __shfl_xor_sync(0xffffffffu, part, 1);

        float logit = (part > 0.f) ? part : NEG_SLOPE * part;
        float w = valid ? __expf(logit) : 0.f;  // max-subtraction dropped: exact
        s_lane += w;                            // counted 8x per edge; /8 later
        a0.x += w * et0.x; a0.y += w * et0.y; a0.z += w * et0.z; a0.w += w * et0.w;
        a1.x += w * et1.x; a1.y += w * et1.y; a1.z += w * et1.z; a1.w += w * et1.w;
    }

    // combine the 4 groups' accumulators (xor 16 then 8)
#pragma unroll
    for (int off = 16; off >= 8; off >>= 1) {
        a0.x += __shfl_xor_sync(0xffffffffu, a0.x, off);
        a0.y += __shfl_xor_sync(0xffffffffu, a0.y, off);
        a0.z += __shfl_xor_sync(0xffffffffu, a0.z, off);
        a0.w += __shfl_xor_sync(0xffffffffu, a0.w, off);
        a1.x += __shfl_xor_sync(0xffffffffu, a1.x, off);
        a1.y += __shfl_xor_sync(0xffffffffu, a1.y, off);
        a1.z += __shfl_xor_sync(0xffffffffu, a1.z, off);
        a1.w += __shfl_xor_sync(0xffffffffu, a1.w, off);
    }
    float s = warp_sum(s_lane) * 0.125f;   // exact: /8 is a power of two

    float4 v0, v1;
    if (end > start) {
        float inv = 1.f / s;
        v0.x = eh0.x + a0.x * inv; v0.y = eh0.y + a0.y * inv;
        v0.z = eh0.z + a0.z * inv; v0.w = eh0.w + a0.w * inv;
        v1.x = eh1.x + a1.x * inv; v1.y = eh1.y + a1.y * inv;
        v1.z = eh1.z + a1.z * inv; v1.w = eh1.w + a1.w * inv;
    } else {
        v0 = eh0; v1 = eh1;        // agg = 0 for nodes with no out-edges
    }

    // row-wise L2 normalize (each dim appears once per group -> /4, exact)
    float nrm2 = warp_sum(dot4(v0, v0) + dot4(v1, v1)) * 0.25f;
    float nrm  = fmaxf(sqrtf(nrm2), 1e-12f);
    float inv_n = 1.f / nrm;
    v0.x *= inv_n; v0.y *= inv_n; v0.z *= inv_n; v0.w *= inv_n;
    v1.x *= inv_n; v1.y *= inv_n; v1.z *= inv_n; v1.w *= inv_n;

    if (FINAL) {
        const float4 e00 = *(const float4*)(ent + warp * D + 8 * gl);
        const float4 e01 = *(const float4*)(ent + warp * D + 8 * gl + 4);
        v0.x = 0.25f * e00.x + 0.5f * eh0.x + v0.x;
        v0.y = 0.25f * e00.y + 0.5f * eh0.y + v0.y;
        v0.z = 0.25f * e00.z + 0.5f * eh0.z + v0.z;
        v0.w = 0.25f * e00.w + 0.5f * eh0.w + v0.w;
        v1.x = 0.25f * e01.x + 0.5f * eh1.x + v1.x;
        v1.y = 0.25f * e01.y + 0.5f * eh1.y + v1.y;
        v1.z = 0.25f * e01.z + 0.5f * eh1.z + v1.z;
        v1.w = 0.25f * e01.w + 0.5f * eh1.w + v1.w;
    }
    if (grp == 0) {
        *(float4*)(eout + warp * D + 8 * gl)     = v0;
        *(float4*)(eout + warp * D + 8 * gl + 4) = v1;
    }
}

// ---------------- launch ----------------
extern "C" void kernel_launch(void* const* d_in, const int* in_sizes, int n_in,
                              void* d_out, int out_size) {
    const void*  ei  = d_in[0];                  // [2, E] int32 or int64
    const void*  et  = d_in[1];                  // [E]    int32 or int64
    const float* ent = (const float*)d_in[2];    // [N, 64]
    const float* rel = (const float*)d_in[3];    // [R, 64]
    const float* W   = (const float*)d_in[4];    // [128, 64]
    float*       res = (float*)d_out;            // [N, 64]

    int E = in_sizes[0] / 2;
    int N = in_sizes[2] / D;

    void* p_embA;
    cudaGetSymbolAddress(&p_embA, g_embA);

    // fused: zero deg/flag + precompute P + dtype detect
    k_init<<<65, 128>>>(W, rel, (const unsigned int*)ei, N);

    // CSR build
    int egrid = (E + 255) / 256;
    k_hist<<<egrid, 256>>>(ei, E);
    int nblk = (N + 1023) / 1024;    // 98 <= 148: co-residency guaranteed
    k_scan<<<nblk, 1024>>>(N, E);
    k_place<<<egrid, 256>>>(ei, et, E);

    // hop 1: ent -> g_embA ; hop 2: g_embA -> res (with fused residual)
    int hgrid = (N + 7) / 8;   // 8 warps per 256-thread block
    k_hop<0><<<hgrid, 256>>>(ent, (float*)p_embA, ent, N);
    k_hop<1><<<hgrid, 256>>>((float*)p_embA, res, ent, N);
}